// round 14
// baseline (speedup 1.0000x reference)
#include <cuda_runtime.h>
#include <cstdint>

#define Bsz 64
#define Dd  512
#define Ll  8192
#define NLn 1000

typedef unsigned long long ull;

// Intermediates (device globals; allocations forbidden). Zero-initialized at
// module load; each call leaves them zeroed again for the next graph replay:
//   k_small<1> zeroes g_zz2 + g_s_pad (only written later by k_small<2>)
//   k_big tail zeroes g_ye1/g_zz1/g_ye2 (never read by k_big)
__device__ __align__(16) float g_ye1 [Bsz*Dd];
__device__ __align__(16) float g_ye2 [Bsz*Dd];
__device__ __align__(16) float g_zz1 [Bsz*Dd];
__device__ __align__(16) float g_zz2 [Bsz*Dd];
__device__ __align__(16) float g_s_pad[Bsz*32];   // s[b] at b*32

__device__ __forceinline__ void cp_async16(void* dst, const void* src) {
    unsigned s = (unsigned)__cvta_generic_to_shared(dst);
    asm volatile("cp.async.cg.shared.global [%0], [%1], 16;" :: "r"(s), "l"(src) : "memory");
}
__device__ __forceinline__ ull pack2(float lo, float hi) {
    ull r; asm("mov.b64 %0, {%1, %2};" : "=l"(r) : "f"(lo), "f"(hi)); return r;
}
__device__ __forceinline__ void unpack2(float& lo, float& hi, ull v) {
    asm("mov.b64 {%0, %1}, %2;" : "=f"(lo), "=f"(hi) : "l"(v));
}
__device__ __forceinline__ void ffma2(ull& d, ull a, ull b) {
    asm("fma.rn.f32x2 %0, %1, %2, %0;" : "+l"(d) : "l"(a), "l"(b));
}
__device__ __forceinline__ void red4(float* p, float v0, float v1, float v2, float v3) {
    asm volatile("red.global.add.v4.f32 [%0], {%1,%2,%3,%4};"
                 :: "l"(p), "f"(v0), "f"(v1), "f"(v2), "f"(v3) : "memory");
}

// ---------------------------------------------------------------------------
// Small residual GEMM: C += A @ W^T, A [64,512], W [512,512].
// CTA 64b x 32e, k-chunk 64, split-K=8, grid(128,2), 256 threads.
// STAGE1: y=0 builds A by direct gather from W_yemb (k_prep deleted);
//         y=1 A = z. Split-0 folds the residual+bias into the RED.
// STAGE2: A = g_ye1/g_zz1; split-0 folds A+b2; y=0 folds w_proj dot -> g_s_pad.
// C starts zero (previous call's k_big tail / module init).
// ---------------------------------------------------------------------------
template<int STAGE>
__global__ void __launch_bounds__(256) k_small(const float* __restrict__ z,
                                               const int* __restrict__ y,
                                               const float* __restrict__ W_yemb,
                                               const float* __restrict__ b_yemb,
                                               const float* __restrict__ Wy,
                                               const float* __restrict__ Wz,
                                               const float* __restrict__ bfy,
                                               const float* __restrict__ bfz,
                                               const float* __restrict__ w_proj) {
    __shared__ float sA[64*68];
    __shared__ float sW[64*32];
    const float* W; const float* bf; float* C;
    const float* A = nullptr;
    if (blockIdx.y == 0) { W = Wy; bf = bfy; C = (STAGE == 1) ? g_ye1 : g_ye2; }
    else                 { W = Wz; bf = bfz; C = (STAGE == 1) ? g_zz1 : g_zz2; }
    if (STAGE == 1) { if (blockIdx.y == 1) A = z; }
    else            { A = (blockIdx.y == 0) ? g_ye1 : g_zz1; }

    const int t  = threadIdx.x;
    const int e0 = (blockIdx.x & 15) * 32;
    const int k0 = (blockIdx.x >> 4) * 64;

    // ---- A tile [64b][64k] -> sA (stride 68) ----
    if (STAGE == 1 && blockIdx.y == 0) {
        // gather: A[b][k] = W_yemb[(k0+k)*NLn + y[b]] + b_yemb[k0+k]
        const int b  = t & 63;
        const int yb = __ldg(y + b);
        #pragma unroll
        for (int j = 0; j < 16; j++) {
            int k = (t >> 6) + 4*j;
            sA[b*68 + k] = __ldg(W_yemb + (k0 + k)*NLn + yb) + b_yemb[k0 + k];
        }
    } else {
        #pragma unroll
        for (int r = 0; r < 4; r++) {
            int id = t + 256*r;
            int b = id >> 4, k4 = id & 15;
            cp_async16(&sA[b*68 + 4*k4], A + b*Dd + k0 + 4*k4);
        }
        asm volatile("cp.async.commit_group;" ::: "memory");
    }
    // ---- W tile [32e][64k] -> sW[k][e] transpose ----
    float4 wv[2]; int we[2], wk[2];
    #pragma unroll
    for (int r = 0; r < 2; r++) {
        int id = t + 256*r;
        we[r] = id >> 4; wk[r] = id & 15;
        wv[r] = *(const float4*)(W + (e0 + we[r])*Dd + k0 + 4*wk[r]);
    }
    #pragma unroll
    for (int r = 0; r < 2; r++) {
        sW[(4*wk[r] + 0)*32 + we[r]] = wv[r].x;
        sW[(4*wk[r] + 1)*32 + we[r]] = wv[r].y;
        sW[(4*wk[r] + 2)*32 + we[r]] = wv[r].z;
        sW[(4*wk[r] + 3)*32 + we[r]] = wv[r].w;
    }
    if (!(STAGE == 1 && blockIdx.y == 0)) {
        asm volatile("cp.async.wait_group 0;" ::: "memory");
    }
    __syncthreads();

    const int b  = t >> 2;
    const int eg = t & 3;
    ull acc[4] = {0, 0, 0, 0};

    #pragma unroll 8
    for (int k = 0; k < 64; k++) {
        float a = sA[b*68 + k];
        ull ap = pack2(a, a);
        ulonglong2 wA = *(const ulonglong2*)&sW[k*32 + eg*8];
        ulonglong2 wB = *(const ulonglong2*)&sW[k*32 + eg*8 + 4];
        ffma2(acc[0], ap, wA.x);
        ffma2(acc[1], ap, wA.y);
        ffma2(acc[2], ap, wB.x);
        ffma2(acc[3], ap, wB.y);
    }

    float v[8];
    unpack2(v[0], v[1], acc[0]);
    unpack2(v[2], v[3], acc[1]);
    unpack2(v[4], v[5], acc[2]);
    unpack2(v[6], v[7], acc[3]);
    const int eo = e0 + eg*8;
    if (k0 == 0) {
        // fold residual init: C starts zero; add (residual + bias) once.
        if (STAGE == 1 && blockIdx.y == 0) {
            const int yb2 = __ldg(y + b);
            #pragma unroll
            for (int i = 0; i < 8; i++)
                v[i] += __ldg(W_yemb + (eo + i)*NLn + yb2) + b_yemb[eo + i] + bf[eo + i];
        } else {
            const float* R = (STAGE == 1) ? z : A;
            float4 p0 = *(const float4*)&R[b*Dd + eo];
            float4 p1 = *(const float4*)&R[b*Dd + eo + 4];
            float4 q0 = *(const float4*)&bf[eo];
            float4 q1 = *(const float4*)&bf[eo + 4];
            v[0] += p0.x + q0.x; v[1] += p0.y + q0.y;
            v[2] += p0.z + q0.z; v[3] += p0.w + q0.w;
            v[4] += p1.x + q1.x; v[5] += p1.y + q1.y;
            v[6] += p1.z + q1.z; v[7] += p1.w + q1.w;
        }
    }
    red4(&C[b*Dd + eo],     v[0], v[1], v[2], v[3]);
    red4(&C[b*Dd + eo + 4], v[4], v[5], v[6], v[7]);

    if (STAGE == 2 && blockIdx.y == 0) {
        float4 wp0 = *(const float4*)&w_proj[eo];
        float4 wp1 = *(const float4*)&w_proj[eo + 4];
        float sp = v[0]*wp0.x + v[1]*wp0.y + v[2]*wp0.z + v[3]*wp0.w
                 + v[4]*wp1.x + v[5]*wp1.y + v[6]*wp1.z + v[7]*wp1.w;
        sp += __shfl_xor_sync(0xffffffffu, sp, 1);
        sp += __shfl_xor_sync(0xffffffffu, sp, 2);
        if (eg == 0) atomicAdd(&g_s_pad[b*32], sp);
    }

    // STAGE1 tail: zero g_zz2 + g_s_pad for this call's k_small<2> atomics.
    if (STAGE == 1) {
        int cid = blockIdx.y*128 + blockIdx.x;          // 0..255
        if (t < 128) g_zz2[cid*128 + t] = 0.f;
        if (cid == 0 && t < 64) g_s_pad[t*32] = 0.f;
    }
}

// ---------------------------------------------------------------------------
// k_big_mma: out[b,l] = s[b] * dot(zz2[b,:], W_zlat[l,:]) via mma.sync bf16
// 3-pass split (AhWh + AhWl + AlWh), fp32 register accumulators.
// CTA 32b x 32l, 128 threads = 4 warps. Grid (256,2)=512 CTAs.
// Depth-2 register prefetch with statically-named sets (no local spill).
// Tail zeroes g_ye1/g_zz1/g_ye2 for the next graph replay.
// ---------------------------------------------------------------------------
#define PITCH 20
__device__ __forceinline__ uint32_t bf2(float lo, float hi) {
    uint32_t r; asm("cvt.rn.bf16x2.f32 %0, %1, %2;" : "=r"(r) : "f"(hi), "f"(lo)); return r;
}
__device__ __forceinline__ void cvt_hilo(float4 f, uint32_t& h0, uint32_t& h1,
                                         uint32_t& l0, uint32_t& l1) {
    h0 = bf2(f.x, f.y);
    h1 = bf2(f.z, f.w);
    float hx = __uint_as_float(h0 << 16), hy = __uint_as_float(h0 & 0xffff0000u);
    float hz = __uint_as_float(h1 << 16), hw = __uint_as_float(h1 & 0xffff0000u);
    l0 = bf2(f.x - hx, f.y - hy);
    l1 = bf2(f.z - hz, f.w - hw);
}
__device__ __forceinline__ void mma16816(float* d, const uint32_t* a,
                                         uint32_t b0, uint32_t b1) {
    asm volatile(
        "mma.sync.aligned.m16n8k16.row.col.f32.bf16.bf16.f32 "
        "{%0,%1,%2,%3},{%4,%5,%6,%7},{%8,%9},{%0,%1,%2,%3};"
        : "+f"(d[0]), "+f"(d[1]), "+f"(d[2]), "+f"(d[3])
        : "r"(a[0]), "r"(a[1]), "r"(a[2]), "r"(a[3]), "r"(b0), "r"(b1));
}

__global__ void __launch_bounds__(128) k_big_mma(const float* __restrict__ Wz,
                                                 float* __restrict__ out) {
    __shared__ uint32_t sAh[2][32*PITCH];
    __shared__ uint32_t sAl[2][32*PITCH];
    __shared__ uint32_t sWh[2][32*PITCH];
    __shared__ uint32_t sWl[2][32*PITCH];
    const int t    = threadIdx.x;
    const int lane = t & 31;
    const int wl   = t >> 5;
    const int g    = lane >> 2;
    const int t4   = lane & 3;
    const int l0   = blockIdx.x * 32;
    const int b0   = blockIdx.y * 32;

    const int ldrow = t >> 3, ldc4 = t & 7;
    const int ldrow2 = (t + 128) >> 3, ldc42 = (t + 128) & 7;
    const int sidx  = ldrow*PITCH + 2*ldc4;
    const int sidx2 = ldrow2*PITCH + 2*ldc42;

    float4 av0_0, av0_1, wv0_0, wv0_1;
    float4 av1_0, av1_1, wv1_0, wv1_1;

#define LDG_SET(a0, a1, w0, w1, c)                                            \
    do {                                                                      \
        a0 = *(const float4*)(g_zz2 + (b0 + ldrow)*Dd + (c)*32 + 4*ldc4);     \
        w0 = *(const float4*)(Wz + (l0 + ldrow)*Dd + (c)*32 + 4*ldc4);        \
        a1 = *(const float4*)(g_zz2 + (b0 + ldrow2)*Dd + (c)*32 + 4*ldc42);   \
        w1 = *(const float4*)(Wz + (l0 + ldrow2)*Dd + (c)*32 + 4*ldc42);      \
    } while (0)

#define STS_SET(buf, a0, a1, w0, w1)                                          \
    do {                                                                      \
        uint32_t h0, h1, q0, q1;                                              \
        cvt_hilo(a0, h0, h1, q0, q1);                                         \
        *(uint2*)&sAh[buf][sidx]  = make_uint2(h0, h1);                       \
        *(uint2*)&sAl[buf][sidx]  = make_uint2(q0, q1);                       \
        cvt_hilo(w0, h0, h1, q0, q1);                                         \
        *(uint2*)&sWh[buf][sidx]  = make_uint2(h0, h1);                       \
        *(uint2*)&sWl[buf][sidx]  = make_uint2(q0, q1);                       \
        cvt_hilo(a1, h0, h1, q0, q1);                                         \
        *(uint2*)&sAh[buf][sidx2] = make_uint2(h0, h1);                       \
        *(uint2*)&sAl[buf][sidx2] = make_uint2(q0, q1);                       \
        cvt_hilo(w1, h0, h1, q0, q1);                                         \
        *(uint2*)&sWh[buf][sidx2] = make_uint2(h0, h1);                       \
        *(uint2*)&sWl[buf][sidx2] = make_uint2(q0, q1);                       \
    } while (0)

    float D[2][4];
    #pragma unroll
    for (int i = 0; i < 2; i++)
        #pragma unroll
        for (int r = 0; r < 4; r++) D[i][r] = 0.f;

    auto compute = [&](const uint32_t* Ah, const uint32_t* Al,
                       const uint32_t* Wh, const uint32_t* Wl) {
        #pragma unroll
        for (int s = 0; s < 2; s++) {
            const int kc = 8*s + t4;
            const int rw = (8*wl + g)*PITCH;
            uint32_t bh0 = Wh[rw + kc], bh1 = Wh[rw + kc + 4];
            uint32_t bl0 = Wl[rw + kc], bl1 = Wl[rw + kc + 4];
            #pragma unroll
            for (int i = 0; i < 2; i++) {
                int r0 = (16*i + g)*PITCH;
                int r1 = r0 + 8*PITCH;
                uint32_t ah[4], al[4];
                ah[0] = Ah[r0 + kc];     ah[1] = Ah[r1 + kc];
                ah[2] = Ah[r0 + kc + 4]; ah[3] = Ah[r1 + kc + 4];
                al[0] = Al[r0 + kc];     al[1] = Al[r1 + kc];
                al[2] = Al[r0 + kc + 4]; al[3] = Al[r1 + kc + 4];
                mma16816(D[i], ah, bh0, bh1);
                mma16816(D[i], ah, bl0, bl1);
                mma16816(D[i], al, bh0, bh1);
            }
        }
    };

    LDG_SET(av0_0, av0_1, wv0_0, wv0_1, 0);
    LDG_SET(av1_0, av1_1, wv1_0, wv1_1, 1);
    #pragma unroll 1
    for (int c2 = 0; c2 < 16; c2 += 2) {
        STS_SET(0, av0_0, av0_1, wv0_0, wv0_1);
        __syncthreads();
        if (c2 + 2 < 16) LDG_SET(av0_0, av0_1, wv0_0, wv0_1, c2 + 2);
        compute(sAh[0], sAl[0], sWh[0], sWl[0]);
        __syncthreads();
        STS_SET(1, av1_0, av1_1, wv1_0, wv1_1);
        __syncthreads();
        if (c2 + 3 < 16) LDG_SET(av1_0, av1_1, wv1_0, wv1_1, c2 + 3);
        compute(sAh[1], sAl[1], sWh[1], sWl[1]);
        __syncthreads();
    }
#undef LDG_SET
#undef STS_SET

    // epilogue: scale by s[b], store
    #pragma unroll
    for (int i = 0; i < 2; i++) {
        const int br = b0 + 16*i + g;
        const float s0 = g_s_pad[br*32];
        const float s1 = g_s_pad[(br + 8)*32];
        const int lc = l0 + 8*wl + 2*t4;
        *(float2*)(out + br*Ll + lc)       = make_float2(D[i][0]*s0, D[i][1]*s0);
        *(float2*)(out + (br + 8)*Ll + lc) = make_float2(D[i][2]*s1, D[i][3]*s1);
    }

    // tail: zero next call's accumulators (k_big never reads these arrays)
    {
        int cid = blockIdx.y*256 + blockIdx.x;     // 0..511
        if (t < 64) {
            g_ye1[cid*64 + t] = 0.f;
            g_zz1[cid*64 + t] = 0.f;
            g_ye2[cid*64 + t] = 0.f;
        }
    }
}

extern "C" void kernel_launch(void* const* d_in, const int* in_sizes, int n_in,
                              void* d_out, int out_size) {
    const float* z      = (const float*)d_in[0];
    const int*   y      = (const int*)  d_in[1];
    const float* W_yemb = (const float*)d_in[2];
    const float* b_yemb = (const float*)d_in[3];
    const float* Wy1    = (const float*)d_in[4];
    const float* by1    = (const float*)d_in[5];
    const float* Wy2    = (const float*)d_in[6];
    const float* by2    = (const float*)d_in[7];
    const float* Wz1    = (const float*)d_in[8];
    const float* bz1    = (const float*)d_in[9];
    const float* Wz2    = (const float*)d_in[10];
    const float* bz2    = (const float*)d_in[11];
    const float* W_zlat = (const float*)d_in[12];
    const float* w_proj = (const float*)d_in[13];
    float* out = (float*)d_out;

    k_small<1><<<dim3(128, 2), 256>>>(z, y, W_yemb, b_yemb, Wy1, Wz1, by1, bz1, nullptr);
    k_small<2><<<dim3(128, 2), 256>>>(z, y, W_yemb, b_yemb, Wy2, Wz2, by2, bz2, w_proj);
    k_big_mma<<<dim3(Ll/32, 2), 128>>>(W_zlat, out);
}

// round 15
// speedup vs baseline: 1.1232x; 1.1232x over previous
#include <cuda_runtime.h>
#include <cstdint>

#define Bsz 64
#define Dd  512
#define Ll  8192
#define NLn 1000

typedef unsigned long long ull;

// Intermediates (device globals; allocations forbidden).
// Never passed as host-side kernel args — kernels reference them directly.
__device__ __align__(16) float g_ye0 [Bsz*Dd];
__device__ __align__(16) float g_ye1 [Bsz*Dd];
__device__ __align__(16) float g_ye2 [Bsz*Dd];
__device__ __align__(16) float g_zz1 [Bsz*Dd];
__device__ __align__(16) float g_zz2 [Bsz*Dd];
__device__ __align__(16) float g_s_pad[Bsz*32];   // s[b] at b*32

__device__ __forceinline__ void cp_async16(void* dst, const void* src) {
    unsigned s = (unsigned)__cvta_generic_to_shared(dst);
    asm volatile("cp.async.cg.shared.global [%0], [%1], 16;" :: "r"(s), "l"(src) : "memory");
}
__device__ __forceinline__ ull pack2(float lo, float hi) {
    ull r; asm("mov.b64 %0, {%1, %2};" : "=l"(r) : "f"(lo), "f"(hi)); return r;
}
__device__ __forceinline__ void unpack2(float& lo, float& hi, ull v) {
    asm("mov.b64 {%0, %1}, %2;" : "=f"(lo), "=f"(hi) : "l"(v));
}
__device__ __forceinline__ void ffma2(ull& d, ull a, ull b) {
    asm("fma.rn.f32x2 %0, %1, %2, %0;" : "+l"(d) : "l"(a), "l"(b));
}
__device__ __forceinline__ void red4(float* p, float v0, float v1, float v2, float v3) {
    asm volatile("red.global.add.v4.f32 [%0], {%1,%2,%3,%4};"
                 :: "l"(p), "f"(v0), "f"(v1), "f"(v2), "f"(v3) : "memory");
}

// ---------------------------------------------------------------------------
// K1: ye0 gather (coalesced, e-parallel), stage-1 residual inits, zero
// stage-2 accumulators + s.  (R14's in-GEMM gather was sector-bound; reverted.)
// ---------------------------------------------------------------------------
__global__ void k_prep(const float* __restrict__ z, const int* __restrict__ y,
                       const float* __restrict__ W_yemb, const float* __restrict__ b_yemb,
                       const float* __restrict__ by1, const float* __restrict__ bz1) {
    int b = blockIdx.x;
    int e = blockIdx.y * 128 + threadIdx.x;
    int yb = __ldg(y + b);
    float v  = __ldg(W_yemb + e*NLn + yb) + b_yemb[e];
    float zv = z[b*Dd + e];
    g_ye0[b*Dd + e] = v;
    g_ye1[b*Dd + e] = v  + by1[e];
    g_zz1[b*Dd + e] = zv + bz1[e];
    g_ye2[b*Dd + e] = 0.f;
    g_zz2[b*Dd + e] = 0.f;
    if (blockIdx.y == 0 && threadIdx.x == 0) g_s_pad[b*32] = 0.f;
}

// ---------------------------------------------------------------------------
// Small residual GEMM (unchanged from passing R5..R13 kernels).
// ---------------------------------------------------------------------------
template<int STAGE>
__global__ void __launch_bounds__(256) k_small(const float* __restrict__ z,
                                               const float* __restrict__ Wy,
                                               const float* __restrict__ Wz,
                                               const float* __restrict__ b2y,
                                               const float* __restrict__ b2z,
                                               const float* __restrict__ w_proj) {
    __shared__ float sA[64*68];
    __shared__ float sW[64*32];
    const float* A; const float* W; const float* b2; float* C;
    if (STAGE == 1) {
        if (blockIdx.y == 0) { A = g_ye0; W = Wy; b2 = nullptr; C = g_ye1; }
        else                 { A = z;     W = Wz; b2 = nullptr; C = g_zz1; }
    } else {
        if (blockIdx.y == 0) { A = g_ye1; W = Wy; b2 = b2y; C = g_ye2; }
        else                 { A = g_zz1; W = Wz; b2 = b2z; C = g_zz2; }
    }
    const int t  = threadIdx.x;
    const int e0 = (blockIdx.x & 15) * 32;
    const int k0 = (blockIdx.x >> 4) * 64;

    #pragma unroll
    for (int r = 0; r < 4; r++) {
        int id = t + 256*r;
        int b = id >> 4, k4 = id & 15;
        cp_async16(&sA[b*68 + 4*k4], A + b*Dd + k0 + 4*k4);
    }
    asm volatile("cp.async.commit_group;" ::: "memory");
    float4 wv[2]; int we[2], wk[2];
    #pragma unroll
    for (int r = 0; r < 2; r++) {
        int id = t + 256*r;
        we[r] = id >> 4; wk[r] = id & 15;
        wv[r] = *(const float4*)(W + (e0 + we[r])*Dd + k0 + 4*wk[r]);
    }
    #pragma unroll
    for (int r = 0; r < 2; r++) {
        sW[(4*wk[r] + 0)*32 + we[r]] = wv[r].x;
        sW[(4*wk[r] + 1)*32 + we[r]] = wv[r].y;
        sW[(4*wk[r] + 2)*32 + we[r]] = wv[r].z;
        sW[(4*wk[r] + 3)*32 + we[r]] = wv[r].w;
    }
    asm volatile("cp.async.wait_group 0;" ::: "memory");
    __syncthreads();

    const int b  = t >> 2;
    const int eg = t & 3;
    ull acc[4] = {0, 0, 0, 0};

    #pragma unroll 8
    for (int k = 0; k < 64; k++) {
        float a = sA[b*68 + k];
        ull ap = pack2(a, a);
        ulonglong2 wA = *(const ulonglong2*)&sW[k*32 + eg*8];
        ulonglong2 wB = *(const ulonglong2*)&sW[k*32 + eg*8 + 4];
        ffma2(acc[0], ap, wA.x);
        ffma2(acc[1], ap, wA.y);
        ffma2(acc[2], ap, wB.x);
        ffma2(acc[3], ap, wB.y);
    }

    float v[8];
    unpack2(v[0], v[1], acc[0]);
    unpack2(v[2], v[3], acc[1]);
    unpack2(v[4], v[5], acc[2]);
    unpack2(v[6], v[7], acc[3]);
    const int eo = e0 + eg*8;
    if (STAGE == 2 && k0 == 0) {
        float4 p0 = *(const float4*)&A[b*Dd + eo];
        float4 p1 = *(const float4*)&A[b*Dd + eo + 4];
        float4 q0 = *(const float4*)&b2[eo];
        float4 q1 = *(const float4*)&b2[eo + 4];
        v[0] += p0.x + q0.x; v[1] += p0.y + q0.y;
        v[2] += p0.z + q0.z; v[3] += p0.w + q0.w;
        v[4] += p1.x + q1.x; v[5] += p1.y + q1.y;
        v[6] += p1.z + q1.z; v[7] += p1.w + q1.w;
    }
    red4(&C[b*Dd + eo],     v[0], v[1], v[2], v[3]);
    red4(&C[b*Dd + eo + 4], v[4], v[5], v[6], v[7]);

    if (STAGE == 2 && blockIdx.y == 0) {
        float4 wp0 = *(const float4*)&w_proj[eo];
        float4 wp1 = *(const float4*)&w_proj[eo + 4];
        float sp = v[0]*wp0.x + v[1]*wp0.y + v[2]*wp0.z + v[3]*wp0.w
                 + v[4]*wp1.x + v[5]*wp1.y + v[6]*wp1.z + v[7]*wp1.w;
        sp += __shfl_xor_sync(0xffffffffu, sp, 1);
        sp += __shfl_xor_sync(0xffffffffu, sp, 2);
        if (eg == 0) atomicAdd(&g_s_pad[b*32], sp);
    }
}

// ---------------------------------------------------------------------------
// k_big_mma: out[b,l] = s[b] * dot(zz2[b,:], W_zlat[l,:]) via mma.sync bf16
// 3-pass split (AhWh + AhWl + AlWh), fp32 register accumulators.
// R10-winning shape: CTA 64b x 32l, grid 256 — but 256 threads = 8 WARPS,
// warp tile 16b x 16l (1 m16 x 2 n8). 13.8 warps/SM for latency coverage.
// Depth-2 static register prefetch (R13-verified, no dynamic indexing).
// smem: bf16-pair uint32 tiles, row pitch 20 -> conflict-free fragment LDS.
// ---------------------------------------------------------------------------
#define PITCH 20
__device__ __forceinline__ uint32_t bf2(float lo, float hi) {
    uint32_t r; asm("cvt.rn.bf16x2.f32 %0, %1, %2;" : "=r"(r) : "f"(hi), "f"(lo)); return r;
}
__device__ __forceinline__ void cvt_hilo(float4 f, uint32_t& h0, uint32_t& h1,
                                         uint32_t& l0, uint32_t& l1) {
    h0 = bf2(f.x, f.y);
    h1 = bf2(f.z, f.w);
    float hx = __uint_as_float(h0 << 16), hy = __uint_as_float(h0 & 0xffff0000u);
    float hz = __uint_as_float(h1 << 16), hw = __uint_as_float(h1 & 0xffff0000u);
    l0 = bf2(f.x - hx, f.y - hy);
    l1 = bf2(f.z - hz, f.w - hw);
}
__device__ __forceinline__ void mma16816(float* d, const uint32_t* a,
                                         uint32_t b0, uint32_t b1) {
    asm volatile(
        "mma.sync.aligned.m16n8k16.row.col.f32.bf16.bf16.f32 "
        "{%0,%1,%2,%3},{%4,%5,%6,%7},{%8,%9},{%0,%1,%2,%3};"
        : "+f"(d[0]), "+f"(d[1]), "+f"(d[2]), "+f"(d[3])
        : "r"(a[0]), "r"(a[1]), "r"(a[2]), "r"(a[3]), "r"(b0), "r"(b1));
}

__global__ void __launch_bounds__(256) k_big_mma(const float* __restrict__ Wz,
                                                 float* __restrict__ out) {
    __shared__ uint32_t sAh[2][64*PITCH];
    __shared__ uint32_t sAl[2][64*PITCH];
    __shared__ uint32_t sWh[2][32*PITCH];
    __shared__ uint32_t sWl[2][32*PITCH];
    const int t    = threadIdx.x;
    const int lane = t & 31;
    const int wid  = t >> 5;          // 0..7
    const int bblk = wid >> 1;        // b rows 16*bblk + g (+8)
    const int lblk = wid & 1;         // l cols 16*lblk + 8j
    const int g    = lane >> 2;       // 0..7
    const int t4   = lane & 3;        // 0..3
    const int l0   = blockIdx.x * 32;

    // producer coords: A tile 64x8 f4 (2/thread), W tile 32x8 f4 (1/thread)
    const int arow0 = t >> 3,          ac4 = t & 7;           // A r=0: rows 0..31
    const int arow1 = arow0 + 32;                             // A r=1: rows 32..63
    const int aidx0 = arow0*PITCH + 2*ac4;
    const int aidx1 = arow1*PITCH + 2*ac4;

    float4 aA0, aA1, aW0;             // staging set 0 (even chunks)
    float4 bA0, bA1, bW0;             // staging set 1 (odd chunks)

#define LDG_SET(x0, x1, w0, c)                                               \
    do {                                                                     \
        x0 = *(const float4*)(g_zz2 + arow0*Dd + (c)*32 + 4*ac4);            \
        x1 = *(const float4*)(g_zz2 + arow1*Dd + (c)*32 + 4*ac4);            \
        w0 = *(const float4*)(Wz + (l0 + arow0)*Dd + (c)*32 + 4*ac4);        \
    } while (0)

#define STS_SET(buf, x0, x1, w0)                                             \
    do {                                                                     \
        uint32_t h0, h1, q0, q1;                                             \
        cvt_hilo(x0, h0, h1, q0, q1);                                        \
        *(uint2*)&sAh[buf][aidx0] = make_uint2(h0, h1);                      \
        *(uint2*)&sAl[buf][aidx0] = make_uint2(q0, q1);                      \
        cvt_hilo(x1, h0, h1, q0, q1);                                        \
        *(uint2*)&sAh[buf][aidx1] = make_uint2(h0, h1);                      \
        *(uint2*)&sAl[buf][aidx1] = make_uint2(q0, q1);                      \
        cvt_hilo(w0, h0, h1, q0, q1);                                        \
        *(uint2*)&sWh[buf][aidx0] = make_uint2(h0, h1);                      \
        *(uint2*)&sWl[buf][aidx0] = make_uint2(q0, q1);                      \
    } while (0)

    float D[2][4];
    #pragma unroll
    for (int j = 0; j < 2; j++)
        #pragma unroll
        for (int r = 0; r < 4; r++) D[j][r] = 0.f;

    auto compute = [&](const uint32_t* Ah, const uint32_t* Al,
                       const uint32_t* Wh, const uint32_t* Wl) {
        #pragma unroll
        for (int s = 0; s < 2; s++) {    // two k16 steps per 32k chunk
            const int kc = 8*s + t4;
            const int r0 = (16*bblk + g)*PITCH;
            const int r1 = r0 + 8*PITCH;
            uint32_t ah[4], al[4];
            ah[0] = Ah[r0 + kc];     ah[1] = Ah[r1 + kc];
            ah[2] = Ah[r0 + kc + 4]; ah[3] = Ah[r1 + kc + 4];
            al[0] = Al[r0 + kc];     al[1] = Al[r1 + kc];
            al[2] = Al[r0 + kc + 4]; al[3] = Al[r1 + kc + 4];
            #pragma unroll
            for (int j = 0; j < 2; j++) {
                const int rw = (16*lblk + 8*j + g)*PITCH;
                uint32_t bh0 = Wh[rw + kc], bh1 = Wh[rw + kc + 4];
                uint32_t bl0 = Wl[rw + kc], bl1 = Wl[rw + kc + 4];
                mma16816(D[j], ah, bh0, bh1);   // Ah*Wh
                mma16816(D[j], ah, bl0, bl1);   // Ah*Wl
                mma16816(D[j], al, bh0, bh1);   // Al*Wh
            }
        }
    };

    LDG_SET(aA0, aA1, aW0, 0);
    LDG_SET(bA0, bA1, bW0, 1);
    #pragma unroll 1
    for (int c2 = 0; c2 < 16; c2 += 2) {
        // even chunk -> buf 0 / set 0
        STS_SET(0, aA0, aA1, aW0);
        __syncthreads();
        if (c2 + 2 < 16) LDG_SET(aA0, aA1, aW0, c2 + 2);
        compute(sAh[0], sAl[0], sWh[0], sWl[0]);
        __syncthreads();
        // odd chunk -> buf 1 / set 1
        STS_SET(1, bA0, bA1, bW0);
        __syncthreads();
        if (c2 + 3 < 16) LDG_SET(bA0, bA1, bW0, c2 + 3);
        compute(sAh[1], sAl[1], sWh[1], sWl[1]);
        __syncthreads();
    }
#undef LDG_SET
#undef STS_SET

    // epilogue: scale by s[b], store float2 (cols 2t4, 2t4+1 contiguous)
    const int br = 16*bblk + g;
    const float s0 = g_s_pad[br*32];
    const float s1 = g_s_pad[(br + 8)*32];
    #pragma unroll
    for (int j = 0; j < 2; j++) {
        const int lc = l0 + 16*lblk + 8*j + 2*t4;
        *(float2*)(out + br*Ll + lc)       = make_float2(D[j][0]*s0, D[j][1]*s0);
        *(float2*)(out + (br + 8)*Ll + lc) = make_float2(D[j][2]*s1, D[j][3]*s1);
    }
}

extern "C" void kernel_launch(void* const* d_in, const int* in_sizes, int n_in,
                              void* d_out, int out_size) {
    const float* z      = (const float*)d_in[0];
    const int*   y      = (const int*)  d_in[1];
    const float* W_yemb = (const float*)d_in[2];
    const float* b_yemb = (const float*)d_in[3];
    const float* Wy1    = (const float*)d_in[4];
    const float* by1    = (const float*)d_in[5];
    const float* Wy2    = (const float*)d_in[6];
    const float* by2    = (const float*)d_in[7];
    const float* Wz1    = (const float*)d_in[8];
    const float* bz1    = (const float*)d_in[9];
    const float* Wz2    = (const float*)d_in[10];
    const float* bz2    = (const float*)d_in[11];
    const float* W_zlat = (const float*)d_in[12];
    const float* w_proj = (const float*)d_in[13];
    float* out = (float*)d_out;

    k_prep<<<dim3(Bsz, 4), 128>>>(z, y, W_yemb, b_yemb, by1, bz1);
    k_small<1><<<dim3(128, 2), 256>>>(z, Wy1, Wz1, nullptr, nullptr, nullptr);
    k_small<2><<<dim3(128, 2), 256>>>(z, Wy2, Wz2, by2, bz2, w_proj);
    k_big_mma<<<Ll/32, 256>>>(W_zlat, out);
}

// round 16
// speedup vs baseline: 1.1945x; 1.0635x over previous
#include <cuda_runtime.h>
#include <cstdint>

#define Bsz 64
#define Dd  512
#define Ll  8192
#define NLn 1000

typedef unsigned long long ull;

// Intermediates (device globals; allocations forbidden).
// Never passed as host-side kernel args — kernels reference them directly.
__device__ __align__(16) float g_ye0 [Bsz*Dd];
__device__ __align__(16) float g_ye1 [Bsz*Dd];
__device__ __align__(16) float g_ye2 [Bsz*Dd];
__device__ __align__(16) float g_zz1 [Bsz*Dd];
__device__ __align__(16) float g_zz2 [Bsz*Dd];
__device__ __align__(16) float g_s_pad[Bsz*32];   // s[b] at b*32

__device__ __forceinline__ void cp_async16(void* dst, const void* src) {
    unsigned s = (unsigned)__cvta_generic_to_shared(dst);
    asm volatile("cp.async.cg.shared.global [%0], [%1], 16;" :: "r"(s), "l"(src) : "memory");
}
__device__ __forceinline__ ull pack2(float lo, float hi) {
    ull r; asm("mov.b64 %0, {%1, %2};" : "=l"(r) : "f"(lo), "f"(hi)); return r;
}
__device__ __forceinline__ void unpack2(float& lo, float& hi, ull v) {
    asm("mov.b64 {%0, %1}, %2;" : "=f"(lo), "=f"(hi) : "l"(v));
}
__device__ __forceinline__ void ffma2(ull& d, ull a, ull b) {
    asm("fma.rn.f32x2 %0, %1, %2, %0;" : "+l"(d) : "l"(a), "l"(b));
}
__device__ __forceinline__ void red4(float* p, float v0, float v1, float v2, float v3) {
    asm volatile("red.global.add.v4.f32 [%0], {%1,%2,%3,%4};"
                 :: "l"(p), "f"(v0), "f"(v1), "f"(v2), "f"(v3) : "memory");
}

// ---------------------------------------------------------------------------
// K1: ye0 gather (coalesced, e-parallel), stage-1 residual inits, zero
// stage-2 accumulators + s.
// ---------------------------------------------------------------------------
__global__ void k_prep(const float* __restrict__ z, const int* __restrict__ y,
                       const float* __restrict__ W_yemb, const float* __restrict__ b_yemb,
                       const float* __restrict__ by1, const float* __restrict__ bz1) {
    int b = blockIdx.x;
    int e = blockIdx.y * 128 + threadIdx.x;
    int yb = __ldg(y + b);
    float v  = __ldg(W_yemb + e*NLn + yb) + b_yemb[e];
    float zv = z[b*Dd + e];
    g_ye0[b*Dd + e] = v;
    g_ye1[b*Dd + e] = v  + by1[e];
    g_zz1[b*Dd + e] = zv + bz1[e];
    g_ye2[b*Dd + e] = 0.f;
    g_zz2[b*Dd + e] = 0.f;
    if (blockIdx.y == 0 && threadIdx.x == 0) g_s_pad[b*32] = 0.f;
}

// ---------------------------------------------------------------------------
// Small residual GEMM (unchanged from passing R5..R15 kernels).
// ---------------------------------------------------------------------------
template<int STAGE>
__global__ void __launch_bounds__(256) k_small(const float* __restrict__ z,
                                               const float* __restrict__ Wy,
                                               const float* __restrict__ Wz,
                                               const float* __restrict__ b2y,
                                               const float* __restrict__ b2z,
                                               const float* __restrict__ w_proj) {
    __shared__ float sA[64*68];
    __shared__ float sW[64*32];
    const float* A; const float* W; const float* b2; float* C;
    if (STAGE == 1) {
        if (blockIdx.y == 0) { A = g_ye0; W = Wy; b2 = nullptr; C = g_ye1; }
        else                 { A = z;     W = Wz; b2 = nullptr; C = g_zz1; }
    } else {
        if (blockIdx.y == 0) { A = g_ye1; W = Wy; b2 = b2y; C = g_ye2; }
        else                 { A = g_zz1; W = Wz; b2 = b2z; C = g_zz2; }
    }
    const int t  = threadIdx.x;
    const int e0 = (blockIdx.x & 15) * 32;
    const int k0 = (blockIdx.x >> 4) * 64;

    #pragma unroll
    for (int r = 0; r < 4; r++) {
        int id = t + 256*r;
        int b = id >> 4, k4 = id & 15;
        cp_async16(&sA[b*68 + 4*k4], A + b*Dd + k0 + 4*k4);
    }
    asm volatile("cp.async.commit_group;" ::: "memory");
    float4 wv[2]; int we[2], wk[2];
    #pragma unroll
    for (int r = 0; r < 2; r++) {
        int id = t + 256*r;
        we[r] = id >> 4; wk[r] = id & 15;
        wv[r] = *(const float4*)(W + (e0 + we[r])*Dd + k0 + 4*wk[r]);
    }
    #pragma unroll
    for (int r = 0; r < 2; r++) {
        sW[(4*wk[r] + 0)*32 + we[r]] = wv[r].x;
        sW[(4*wk[r] + 1)*32 + we[r]] = wv[r].y;
        sW[(4*wk[r] + 2)*32 + we[r]] = wv[r].z;
        sW[(4*wk[r] + 3)*32 + we[r]] = wv[r].w;
    }
    asm volatile("cp.async.wait_group 0;" ::: "memory");
    __syncthreads();

    const int b  = t >> 2;
    const int eg = t & 3;
    ull acc[4] = {0, 0, 0, 0};

    #pragma unroll 8
    for (int k = 0; k < 64; k++) {
        float a = sA[b*68 + k];
        ull ap = pack2(a, a);
        ulonglong2 wA = *(const ulonglong2*)&sW[k*32 + eg*8];
        ulonglong2 wB = *(const ulonglong2*)&sW[k*32 + eg*8 + 4];
        ffma2(acc[0], ap, wA.x);
        ffma2(acc[1], ap, wA.y);
        ffma2(acc[2], ap, wB.x);
        ffma2(acc[3], ap, wB.y);
    }

    float v[8];
    unpack2(v[0], v[1], acc[0]);
    unpack2(v[2], v[3], acc[1]);
    unpack2(v[4], v[5], acc[2]);
    unpack2(v[6], v[7], acc[3]);
    const int eo = e0 + eg*8;
    if (STAGE == 2 && k0 == 0) {
        float4 p0 = *(const float4*)&A[b*Dd + eo];
        float4 p1 = *(const float4*)&A[b*Dd + eo + 4];
        float4 q0 = *(const float4*)&b2[eo];
        float4 q1 = *(const float4*)&b2[eo + 4];
        v[0] += p0.x + q0.x; v[1] += p0.y + q0.y;
        v[2] += p0.z + q0.z; v[3] += p0.w + q0.w;
        v[4] += p1.x + q1.x; v[5] += p1.y + q1.y;
        v[6] += p1.z + q1.z; v[7] += p1.w + q1.w;
    }
    red4(&C[b*Dd + eo],     v[0], v[1], v[2], v[3]);
    red4(&C[b*Dd + eo + 4], v[4], v[5], v[6], v[7]);

    if (STAGE == 2 && blockIdx.y == 0) {
        float4 wp0 = *(const float4*)&w_proj[eo];
        float4 wp1 = *(const float4*)&w_proj[eo + 4];
        float sp = v[0]*wp0.x + v[1]*wp0.y + v[2]*wp0.z + v[3]*wp0.w
                 + v[4]*wp1.x + v[5]*wp1.y + v[6]*wp1.z + v[7]*wp1.w;
        sp += __shfl_xor_sync(0xffffffffu, sp, 1);
        sp += __shfl_xor_sync(0xffffffffu, sp, 2);
        if (eg == 0) atomicAdd(&g_s_pad[b*32], sp);
    }
}

// ---------------------------------------------------------------------------
// k_big_mma: out[b,l] = s[b] * dot(zz2[b,:], W_zlat[l,:]) via mma.sync bf16
// 3-pass split (AhWh + AhWl + AlWh), fp32 register accumulators.
// CTA 64b x 32l, 256 threads = 8 warps (warp 16b x 16l), grid 256.
// NEW: ldmatrix.m8n8.x4 fragment loads (8 LDSM vs 32 LDS per warp-chunk;
// pitch-20 rows give a perfect 32-bank cover per 8-row quadrant) and a
// single __syncthreads per chunk (compute -> STS(next) -> LDG(+2) -> sync).
// Depth-2 static register staging (R13-proven, no dynamic indexing).
// ---------------------------------------------------------------------------
#define PITCH 20
__device__ __forceinline__ uint32_t bf2(float lo, float hi) {
    uint32_t r; asm("cvt.rn.bf16x2.f32 %0, %1, %2;" : "=r"(r) : "f"(hi), "f"(lo)); return r;
}
__device__ __forceinline__ void cvt_hilo(float4 f, uint32_t& h0, uint32_t& h1,
                                         uint32_t& l0, uint32_t& l1) {
    h0 = bf2(f.x, f.y);
    h1 = bf2(f.z, f.w);
    float hx = __uint_as_float(h0 << 16), hy = __uint_as_float(h0 & 0xffff0000u);
    float hz = __uint_as_float(h1 << 16), hw = __uint_as_float(h1 & 0xffff0000u);
    l0 = bf2(f.x - hx, f.y - hy);
    l1 = bf2(f.z - hz, f.w - hw);
}
__device__ __forceinline__ void mma16816(float* d, const uint32_t* a,
                                         uint32_t b0, uint32_t b1) {
    asm volatile(
        "mma.sync.aligned.m16n8k16.row.col.f32.bf16.bf16.f32 "
        "{%0,%1,%2,%3},{%4,%5,%6,%7},{%8,%9},{%0,%1,%2,%3};"
        : "+f"(d[0]), "+f"(d[1]), "+f"(d[2]), "+f"(d[3])
        : "r"(a[0]), "r"(a[1]), "r"(a[2]), "r"(a[3]), "r"(b0), "r"(b1));
}
__device__ __forceinline__ void ldsm4(uint32_t* r, uint32_t addr) {
    asm volatile("ldmatrix.sync.aligned.m8n8.x4.shared.b16 {%0,%1,%2,%3}, [%4];"
                 : "=r"(r[0]), "=r"(r[1]), "=r"(r[2]), "=r"(r[3]) : "r"(addr));
}
__device__ __forceinline__ uint32_t smem_u32(const void* p) {
    return (uint32_t)__cvta_generic_to_shared(p);
}

__global__ void __launch_bounds__(256) k_big_mma(const float* __restrict__ Wz,
                                                 float* __restrict__ out) {
    __shared__ uint32_t sAh[2][64*PITCH];
    __shared__ uint32_t sAl[2][64*PITCH];
    __shared__ uint32_t sWh[2][32*PITCH];
    __shared__ uint32_t sWl[2][32*PITCH];
    const int t    = threadIdx.x;
    const int lane = t & 31;
    const int wid  = t >> 5;          // 0..7
    const int bblk = wid >> 1;        // b rows 16*bblk + g (+8)
    const int lblk = wid & 1;         // l cols 16*lblk + 8j
    const int g    = lane >> 2;       // 0..7
    const int t4   = lane & 3;        // 0..3
    const int l0   = blockIdx.x * 32;

    // producer coords: A tile 64x8 f4 (2/thread), W tile 32x8 f4 (1/thread)
    const int arow0 = t >> 3, ac4 = t & 7;       // A r=0: rows 0..31
    const int arow1 = arow0 + 32;                // A r=1: rows 32..63
    const int aidx0 = arow0*PITCH + 2*ac4;
    const int aidx1 = arow1*PITCH + 2*ac4;

    // ldmatrix lane-address fragment indices (uint32 units):
    //   lanes 0-15 -> rows (lane&15), lanes 16-31 -> same rows, k-quad +4
    const int afrag = (16*bblk + (lane & 15))*PITCH + ((lane >> 4) << 2);
    const int wfrag = (16*lblk + (lane & 15))*PITCH + ((lane >> 4) << 2);
    const uint32_t aAh0 = smem_u32(&sAh[0][afrag]), aAh1 = smem_u32(&sAh[1][afrag]);
    const uint32_t aAl0 = smem_u32(&sAl[0][afrag]), aAl1 = smem_u32(&sAl[1][afrag]);
    const uint32_t aWh0 = smem_u32(&sWh[0][wfrag]), aWh1 = smem_u32(&sWh[1][wfrag]);
    const uint32_t aWl0 = smem_u32(&sWl[0][wfrag]), aWl1 = smem_u32(&sWl[1][wfrag]);

    float4 aA0, aA1, aW0;             // staging set A (even-ish)
    float4 bA0, bA1, bW0;             // staging set B (odd-ish)

#define LDG_SET(x0, x1, w0, c)                                               \
    do {                                                                     \
        x0 = *(const float4*)(g_zz2 + arow0*Dd + (c)*32 + 4*ac4);            \
        x1 = *(const float4*)(g_zz2 + arow1*Dd + (c)*32 + 4*ac4);            \
        w0 = *(const float4*)(Wz + (l0 + arow0)*Dd + (c)*32 + 4*ac4);        \
    } while (0)

#define STS_SET(buf, x0, x1, w0)                                             \
    do {                                                                     \
        uint32_t h0, h1, q0, q1;                                             \
        cvt_hilo(x0, h0, h1, q0, q1);                                        \
        *(uint2*)&sAh[buf][aidx0] = make_uint2(h0, h1);                      \
        *(uint2*)&sAl[buf][aidx0] = make_uint2(q0, q1);                      \
        cvt_hilo(x1, h0, h1, q0, q1);                                        \
        *(uint2*)&sAh[buf][aidx1] = make_uint2(h0, h1);                      \
        *(uint2*)&sAl[buf][aidx1] = make_uint2(q0, q1);                      \
        cvt_hilo(w0, h0, h1, q0, q1);                                        \
        *(uint2*)&sWh[buf][aidx0] = make_uint2(h0, h1);                      \
        *(uint2*)&sWl[buf][aidx0] = make_uint2(q0, q1);                      \
    } while (0)

    float D[2][4];
    #pragma unroll
    for (int j = 0; j < 2; j++)
        #pragma unroll
        for (int r = 0; r < 4; r++) D[j][r] = 0.f;

    // LDSM fragment layout: A x4 -> {a0,a1,a2,a3} exactly the mma A order;
    // W x4 over the 16-row (two n8 tiles) block -> r0/r2 = j0 {b0,b1},
    // r1/r3 = j1 {b0,b1}.
    auto compute = [&](uint32_t ah_b, uint32_t al_b, uint32_t wh_b, uint32_t wl_b) {
        #pragma unroll
        for (int s = 0; s < 2; s++) {
            uint32_t ah[4], al[4], wh[4], wl[4];
            ldsm4(ah, ah_b + 32*s);
            ldsm4(al, al_b + 32*s);
            ldsm4(wh, wh_b + 32*s);
            ldsm4(wl, wl_b + 32*s);
            mma16816(D[0], ah, wh[0], wh[2]);
            mma16816(D[0], ah, wl[0], wl[2]);
            mma16816(D[0], al, wh[0], wh[2]);
            mma16816(D[1], ah, wh[1], wh[3]);
            mma16816(D[1], ah, wl[1], wl[3]);
            mma16816(D[1], al, wh[1], wh[3]);
        }
    };

    // prologue: Ra=chunk0 -> buf0; Rb=chunk1; Ra refilled with chunk2
    LDG_SET(aA0, aA1, aW0, 0);
    LDG_SET(bA0, bA1, bW0, 1);
    STS_SET(0, aA0, aA1, aW0);
    LDG_SET(aA0, aA1, aW0, 2);
    __syncthreads();

    #pragma unroll 1
    for (int c2 = 0; c2 < 16; c2 += 2) {
        // chunk c2 (buf0)
        compute(aAh0, aAl0, aWh0, aWl0);
        STS_SET(1, bA0, bA1, bW0);                       // chunk c2+1 -> buf1
        if (c2 + 3 < 16) LDG_SET(bA0, bA1, bW0, c2 + 3);
        __syncthreads();
        // chunk c2+1 (buf1)
        compute(aAh1, aAl1, aWh1, aWl1);
        if (c2 + 2 < 16) {
            STS_SET(0, aA0, aA1, aW0);                   // chunk c2+2 -> buf0
            if (c2 + 4 < 16) LDG_SET(aA0, aA1, aW0, c2 + 4);
        }
        __syncthreads();
    }
#undef LDG_SET
#undef STS_SET

    // epilogue: scale by s[b], store float2 (cols 2t4, 2t4+1 contiguous)
    const int br = 16*bblk + g;
    const float s0 = g_s_pad[br*32];
    const float s1 = g_s_pad[(br + 8)*32];
    #pragma unroll
    for (int j = 0; j < 2; j++) {
        const int lc = l0 + 16*lblk + 8*j + 2*t4;
        *(float2*)(out + br*Ll + lc)       = make_float2(D[j][0]*s0, D[j][1]*s0);
        *(float2*)(out + (br + 8)*Ll + lc) = make_float2(D[j][2]*s1, D[j][3]*s1);
    }
}

extern "C" void kernel_launch(void* const* d_in, const int* in_sizes, int n_in,
                              void* d_out, int out_size) {
    const float* z      = (const float*)d_in[0];
    const int*   y      = (const int*)  d_in[1];
    const float* W_yemb = (const float*)d_in[2];
    const float* b_yemb = (const float*)d_in[3];
    const float* Wy1    = (const float*)d_in[4];
    const float* by1    = (const float*)d_in[5];
    const float* Wy2    = (const float*)d_in[6];
    const float* by2    = (const float*)d_in[7];
    const float* Wz1    = (const float*)d_in[8];
    const float* bz1    = (const float*)d_in[9];
    const float* Wz2    = (const float*)d_in[10];
    const float* bz2    = (const float*)d_in[11];
    const float* W_zlat = (const float*)d_in[12];
    const float* w_proj = (const float*)d_in[13];
    float* out = (float*)d_out;

    k_prep<<<dim3(Bsz, 4), 128>>>(z, y, W_yemb, b_yemb, by1, bz1);
    k_small<1><<<dim3(128, 2), 256>>>(z, Wy1, Wz1, nullptr, nullptr, nullptr);
    k_small<2><<<dim3(128, 2), 256>>>(z, Wy2, Wz2, by2, bz2, w_proj);
    k_big_mma<<<Ll/32, 256>>>(W_zlat, out);
}

// round 17
// speedup vs baseline: 1.1957x; 1.0010x over previous
#include <cuda_runtime.h>
#include <cstdint>

#define Bsz 64
#define Dd  512
#define Ll  8192
#define NLn 1000

typedef unsigned long long ull;

// Intermediates (device globals; allocations forbidden).
// Never passed as host-side kernel args — kernels reference them directly.
__device__ __align__(16) float g_ye0 [Bsz*Dd];
__device__ __align__(16) float g_ye1 [Bsz*Dd];
__device__ __align__(16) float g_ye2 [Bsz*Dd];
__device__ __align__(16) float g_zz1 [Bsz*Dd];
__device__ __align__(16) float g_zz2 [Bsz*Dd];
__device__ __align__(16) float g_s_pad[Bsz*32];   // s[b] at b*32

__device__ __forceinline__ void cp_async16(void* dst, const void* src) {
    unsigned s = (unsigned)__cvta_generic_to_shared(dst);
    asm volatile("cp.async.cg.shared.global [%0], [%1], 16;" :: "r"(s), "l"(src) : "memory");
}
__device__ __forceinline__ ull pack2(float lo, float hi) {
    ull r; asm("mov.b64 %0, {%1, %2};" : "=l"(r) : "f"(lo), "f"(hi)); return r;
}
__device__ __forceinline__ void unpack2(float& lo, float& hi, ull v) {
    asm("mov.b64 {%0, %1}, %2;" : "=f"(lo), "=f"(hi) : "l"(v));
}
__device__ __forceinline__ void ffma2(ull& d, ull a, ull b) {
    asm("fma.rn.f32x2 %0, %1, %2, %0;" : "+l"(d) : "l"(a), "l"(b));
}
__device__ __forceinline__ void red4(float* p, float v0, float v1, float v2, float v3) {
    asm volatile("red.global.add.v4.f32 [%0], {%1,%2,%3,%4};"
                 :: "l"(p), "f"(v0), "f"(v1), "f"(v2), "f"(v3) : "memory");
}

// ---------------------------------------------------------------------------
// K1: ye0 gather (coalesced, e-parallel), stage-1 residual inits, zero
// stage-2 accumulators + s.
// ---------------------------------------------------------------------------
__global__ void k_prep(const float* __restrict__ z, const int* __restrict__ y,
                       const float* __restrict__ W_yemb, const float* __restrict__ b_yemb,
                       const float* __restrict__ by1, const float* __restrict__ bz1) {
    int b = blockIdx.x;
    int e = blockIdx.y * 128 + threadIdx.x;
    int yb = __ldg(y + b);
    float v  = __ldg(W_yemb + e*NLn + yb) + b_yemb[e];
    float zv = z[b*Dd + e];
    g_ye0[b*Dd + e] = v;
    g_ye1[b*Dd + e] = v  + by1[e];
    g_zz1[b*Dd + e] = zv + bz1[e];
    g_ye2[b*Dd + e] = 0.f;
    g_zz2[b*Dd + e] = 0.f;
    if (blockIdx.y == 0 && threadIdx.x == 0) g_s_pad[b*32] = 0.f;
}

// ---------------------------------------------------------------------------
// Small residual GEMM: C += A @ W^T, A [64,512], W [512,512].
// SPLIT-K 16: CTA 64b x 32e, k-chunk 32, grid(16*16, 2) = 512 CTAs
// (3.46 CTAs/SM) so the one-shot load latency overlaps across CTAs.
// e-paired FFMA2 accumulators -> red.global.add.v4.f32 epilogue.
// STAGE2: split-0 folds residual (A + b2); y=0 folds w_proj dot -> g_s_pad.
// ---------------------------------------------------------------------------
template<int STAGE>
__global__ void __launch_bounds__(256) k_small(const float* __restrict__ z,
                                               const float* __restrict__ Wy,
                                               const float* __restrict__ Wz,
                                               const float* __restrict__ b2y,
                                               const float* __restrict__ b2z,
                                               const float* __restrict__ w_proj) {
    __shared__ float sA[64*36];   // [b][k] pad 36 (broadcast reads, 4b-bank spread)
    __shared__ float sW[32*32];   // [k][e] transposed
    const float* A; const float* W; const float* b2; float* C;
    if (STAGE == 1) {
        if (blockIdx.y == 0) { A = g_ye0; W = Wy; b2 = nullptr; C = g_ye1; }
        else                 { A = z;     W = Wz; b2 = nullptr; C = g_zz1; }
    } else {
        if (blockIdx.y == 0) { A = g_ye1; W = Wy; b2 = b2y; C = g_ye2; }
        else                 { A = g_zz1; W = Wz; b2 = b2z; C = g_zz2; }
    }
    const int t  = threadIdx.x;
    const int e0 = (blockIdx.x & 15) * 32;
    const int k0 = (blockIdx.x >> 4) * 32;

    // A tile [64b][32k] via cp.async (512 f4, 2/thread)
    #pragma unroll
    for (int r = 0; r < 2; r++) {
        int id = t + 256*r;              // 0..511
        int b = id >> 3, k4 = id & 7;
        cp_async16(&sA[b*36 + 4*k4], A + b*Dd + k0 + 4*k4);
    }
    asm volatile("cp.async.commit_group;" ::: "memory");
    // W tile [32e][32k] -> sW[k][e] transpose via LDG + STS (256 f4, 1/thread)
    {
        int e = t >> 3, k4 = t & 7;
        float4 wv = *(const float4*)(W + (e0 + e)*Dd + k0 + 4*k4);
        sW[(4*k4 + 0)*32 + e] = wv.x;
        sW[(4*k4 + 1)*32 + e] = wv.y;
        sW[(4*k4 + 2)*32 + e] = wv.z;
        sW[(4*k4 + 3)*32 + e] = wv.w;
    }
    asm volatile("cp.async.wait_group 0;" ::: "memory");
    __syncthreads();

    const int b  = t >> 2;
    const int eg = t & 3;
    ull acc[4] = {0, 0, 0, 0};

    #pragma unroll 8
    for (int k = 0; k < 32; k++) {
        float a = sA[b*36 + k];
        ull ap = pack2(a, a);
        ulonglong2 wA = *(const ulonglong2*)&sW[k*32 + eg*8];
        ulonglong2 wB = *(const ulonglong2*)&sW[k*32 + eg*8 + 4];
        ffma2(acc[0], ap, wA.x);
        ffma2(acc[1], ap, wA.y);
        ffma2(acc[2], ap, wB.x);
        ffma2(acc[3], ap, wB.y);
    }

    float v[8];
    unpack2(v[0], v[1], acc[0]);
    unpack2(v[2], v[3], acc[1]);
    unpack2(v[4], v[5], acc[2]);
    unpack2(v[6], v[7], acc[3]);
    const int eo = e0 + eg*8;
    if (STAGE == 2 && k0 == 0) {
        float4 p0 = *(const float4*)&A[b*Dd + eo];
        float4 p1 = *(const float4*)&A[b*Dd + eo + 4];
        float4 q0 = *(const float4*)&b2[eo];
        float4 q1 = *(const float4*)&b2[eo + 4];
        v[0] += p0.x + q0.x; v[1] += p0.y + q0.y;
        v[2] += p0.z + q0.z; v[3] += p0.w + q0.w;
        v[4] += p1.x + q1.x; v[5] += p1.y + q1.y;
        v[6] += p1.z + q1.z; v[7] += p1.w + q1.w;
    }
    red4(&C[b*Dd + eo],     v[0], v[1], v[2], v[3]);
    red4(&C[b*Dd + eo + 4], v[4], v[5], v[6], v[7]);

    if (STAGE == 2 && blockIdx.y == 0) {
        float4 wp0 = *(const float4*)&w_proj[eo];
        float4 wp1 = *(const float4*)&w_proj[eo + 4];
        float sp = v[0]*wp0.x + v[1]*wp0.y + v[2]*wp0.z + v[3]*wp0.w
                 + v[4]*wp1.x + v[5]*wp1.y + v[6]*wp1.z + v[7]*wp1.w;
        sp += __shfl_xor_sync(0xffffffffu, sp, 1);
        sp += __shfl_xor_sync(0xffffffffu, sp, 2);
        if (eg == 0) atomicAdd(&g_s_pad[b*32], sp);
    }
}

// ---------------------------------------------------------------------------
// k_big_mma (unchanged from passing R16 kernel): mma.sync bf16 3-pass split,
// CTA 64b x 32l, 256 threads = 8 warps, grid 256, ldmatrix fragments,
// single sync per chunk, depth-2 static register staging.
// ---------------------------------------------------------------------------
#define PITCH 20
__device__ __forceinline__ uint32_t bf2(float lo, float hi) {
    uint32_t r; asm("cvt.rn.bf16x2.f32 %0, %1, %2;" : "=r"(r) : "f"(hi), "f"(lo)); return r;
}
__device__ __forceinline__ void cvt_hilo(float4 f, uint32_t& h0, uint32_t& h1,
                                         uint32_t& l0, uint32_t& l1) {
    h0 = bf2(f.x, f.y);
    h1 = bf2(f.z, f.w);
    float hx = __uint_as_float(h0 << 16), hy = __uint_as_float(h0 & 0xffff0000u);
    float hz = __uint_as_float(h1 << 16), hw = __uint_as_float(h1 & 0xffff0000u);
    l0 = bf2(f.x - hx, f.y - hy);
    l1 = bf2(f.z - hz, f.w - hw);
}
__device__ __forceinline__ void mma16816(float* d, const uint32_t* a,
                                         uint32_t b0, uint32_t b1) {
    asm volatile(
        "mma.sync.aligned.m16n8k16.row.col.f32.bf16.bf16.f32 "
        "{%0,%1,%2,%3},{%4,%5,%6,%7},{%8,%9},{%0,%1,%2,%3};"
        : "+f"(d[0]), "+f"(d[1]), "+f"(d[2]), "+f"(d[3])
        : "r"(a[0]), "r"(a[1]), "r"(a[2]), "r"(a[3]), "r"(b0), "r"(b1));
}
__device__ __forceinline__ void ldsm4(uint32_t* r, uint32_t addr) {
    asm volatile("ldmatrix.sync.aligned.m8n8.x4.shared.b16 {%0,%1,%2,%3}, [%4];"
                 : "=r"(r[0]), "=r"(r[1]), "=r"(r[2]), "=r"(r[3]) : "r"(addr));
}
__device__ __forceinline__ uint32_t smem_u32(const void* p) {
    return (uint32_t)__cvta_generic_to_shared(p);
}

__global__ void __launch_bounds__(256) k_big_mma(const float* __restrict__ Wz,
                                                 float* __restrict__ out) {
    __shared__ uint32_t sAh[2][64*PITCH];
    __shared__ uint32_t sAl[2][64*PITCH];
    __shared__ uint32_t sWh[2][32*PITCH];
    __shared__ uint32_t sWl[2][32*PITCH];
    const int t    = threadIdx.x;
    const int lane = t & 31;
    const int wid  = t >> 5;
    const int bblk = wid >> 1;
    const int lblk = wid & 1;
    const int g    = lane >> 2;
    const int t4   = lane & 3;
    const int l0   = blockIdx.x * 32;

    const int arow0 = t >> 3, ac4 = t & 7;
    const int arow1 = arow0 + 32;
    const int aidx0 = arow0*PITCH + 2*ac4;
    const int aidx1 = arow1*PITCH + 2*ac4;

    const int afrag = (16*bblk + (lane & 15))*PITCH + ((lane >> 4) << 2);
    const int wfrag = (16*lblk + (lane & 15))*PITCH + ((lane >> 4) << 2);
    const uint32_t aAh0 = smem_u32(&sAh[0][afrag]), aAh1 = smem_u32(&sAh[1][afrag]);
    const uint32_t aAl0 = smem_u32(&sAl[0][afrag]), aAl1 = smem_u32(&sAl[1][afrag]);
    const uint32_t aWh0 = smem_u32(&sWh[0][wfrag]), aWh1 = smem_u32(&sWh[1][wfrag]);
    const uint32_t aWl0 = smem_u32(&sWl[0][wfrag]), aWl1 = smem_u32(&sWl[1][wfrag]);

    float4 aA0, aA1, aW0;
    float4 bA0, bA1, bW0;

#define LDG_SET(x0, x1, w0, c)                                               \
    do {                                                                     \
        x0 = *(const float4*)(g_zz2 + arow0*Dd + (c)*32 + 4*ac4);            \
        x1 = *(const float4*)(g_zz2 + arow1*Dd + (c)*32 + 4*ac4);            \
        w0 = *(const float4*)(Wz + (l0 + arow0)*Dd + (c)*32 + 4*ac4);        \
    } while (0)

#define STS_SET(buf, x0, x1, w0)                                             \
    do {                                                                     \
        uint32_t h0, h1, q0, q1;                                             \
        cvt_hilo(x0, h0, h1, q0, q1);                                        \
        *(uint2*)&sAh[buf][aidx0] = make_uint2(h0, h1);                      \
        *(uint2*)&sAl[buf][aidx0] = make_uint2(q0, q1);                      \
        cvt_hilo(x1, h0, h1, q0, q1);                                        \
        *(uint2*)&sAh[buf][aidx1] = make_uint2(h0, h1);                      \
        *(uint2*)&sAl[buf][aidx1] = make_uint2(q0, q1);                      \
        cvt_hilo(w0, h0, h1, q0, q1);                                        \
        *(uint2*)&sWh[buf][aidx0] = make_uint2(h0, h1);                      \
        *(uint2*)&sWl[buf][aidx0] = make_uint2(q0, q1);                      \
    } while (0)

    float D[2][4];
    #pragma unroll
    for (int j = 0; j < 2; j++)
        #pragma unroll
        for (int r = 0; r < 4; r++) D[j][r] = 0.f;

    auto compute = [&](uint32_t ah_b, uint32_t al_b, uint32_t wh_b, uint32_t wl_b) {
        #pragma unroll
        for (int s = 0; s < 2; s++) {
            uint32_t ah[4], al[4], wh[4], wl[4];
            ldsm4(ah, ah_b + 32*s);
            ldsm4(al, al_b + 32*s);
            ldsm4(wh, wh_b + 32*s);
            ldsm4(wl, wl_b + 32*s);
            mma16816(D[0], ah, wh[0], wh[2]);
            mma16816(D[0], ah, wl[0], wl[2]);
            mma16816(D[0], al, wh[0], wh[2]);
            mma16816(D[1], ah, wh[1], wh[3]);
            mma16816(D[1], ah, wl[1], wl[3]);
            mma16816(D[1], al, wh[1], wh[3]);
        }
    };

    LDG_SET(aA0, aA1, aW0, 0);
    LDG_SET(bA0, bA1, bW0, 1);
    STS_SET(0, aA0, aA1, aW0);
    LDG_SET(aA0, aA1, aW0, 2);
    __syncthreads();

    #pragma unroll 1
    for (int c2 = 0; c2 < 16; c2 += 2) {
        compute(aAh0, aAl0, aWh0, aWl0);
        STS_SET(1, bA0, bA1, bW0);
        if (c2 + 3 < 16) LDG_SET(bA0, bA1, bW0, c2 + 3);
        __syncthreads();
        compute(aAh1, aAl1, aWh1, aWl1);
        if (c2 + 2 < 16) {
            STS_SET(0, aA0, aA1, aW0);
            if (c2 + 4 < 16) LDG_SET(aA0, aA1, aW0, c2 + 4);
        }
        __syncthreads();
    }
#undef LDG_SET
#undef STS_SET

    const int br = 16*bblk + g;
    const float s0 = g_s_pad[br*32];
    const float s1 = g_s_pad[(br + 8)*32];
    #pragma unroll
    for (int j = 0; j < 2; j++) {
        const int lc = l0 + 16*lblk + 8*j + 2*t4;
        *(float2*)(out + br*Ll + lc)       = make_float2(D[j][0]*s0, D[j][1]*s0);
        *(float2*)(out + (br + 8)*Ll + lc) = make_float2(D[j][2]*s1, D[j][3]*s1);
    }
}

extern "C" void kernel_launch(void* const* d_in, const int* in_sizes, int n_in,
                              void* d_out, int out_size) {
    const float* z      = (const float*)d_in[0];
    const int*   y      = (const int*)  d_in[1];
    const float* W_yemb = (const float*)d_in[2];
    const float* b_yemb = (const float*)d_in[3];
    const float* Wy1    = (const float*)d_in[4];
    const float* by1    = (const float*)d_in[5];
    const float* Wy2    = (const float*)d_in[6];
    const float* by2    = (const float*)d_in[7];
    const float* Wz1    = (const float*)d_in[8];
    const float* bz1    = (const float*)d_in[9];
    const float* Wz2    = (const float*)d_in[10];
    const float* bz2    = (const float*)d_in[11];
    const float* W_zlat = (const float*)d_in[12];
    const float* w_proj = (const float*)d_in[13];
    float* out = (float*)d_out;

    k_prep<<<dim3(Bsz, 4), 128>>>(z, y, W_yemb, b_yemb, by1, bz1);
    k_small<1><<<dim3(256, 2), 256>>>(z, Wy1, Wz1, nullptr, nullptr, nullptr);
    k_small<2><<<dim3(256, 2), 256>>>(z, Wy2, Wz2, by2, bz2, w_proj);
    k_big_mma<<<Ll/32, 256>>>(W_zlat, out);
}